// round 2
// baseline (speedup 1.0000x reference)
#include <cuda_runtime.h>

#define N_NODES  50000
#define N_EDGES  800000
#define IN_CH    128
#define HID      64
#define N_GRAPHS 512
#define OUT_CH   10

// ---------------- scratch (static device memory; no allocations) ------------
__device__ float g_bufA[N_NODES * HID];
__device__ float g_bufB[N_NODES * HID];
__device__ float g_bufC[N_NODES * HID];
__device__ float g_pooled[N_GRAPHS * HID];

// ---------------- zero kernel ----------------------------------------------
__global__ void zero_kernel(float4* __restrict__ p, int n4) {
    int i = blockIdx.x * blockDim.x + threadIdx.x;
    int stride = gridDim.x * blockDim.x;
    for (; i < n4; i += stride) p[i] = make_float4(0.f, 0.f, 0.f, 0.f);
}

// ---------------- fused linear kernel ---------------------------------------
// out[N,64] = EPI ? relu(in @ W + bias) : in @ W
// where in = COMBINE ? relu((1+eps)*A + G + preb) : A
// A: [N,K] row-major, W: [K,64] row-major.
template <int K, bool COMBINE, bool EPI>
__global__ void __launch_bounds__(256) linear_kernel(
    const float* __restrict__ A, const float* __restrict__ G,
    const float* __restrict__ epsp, const float* __restrict__ preb,
    const float* __restrict__ W, const float* __restrict__ bias,
    float* __restrict__ out)
{
    __shared__ float sX[64][68];   // 64 rows x 64 k (padded)
    __shared__ float sW[64][64];   // 64 k x 64 cols

    const int tid = threadIdx.x;
    const int tc = tid & 15;       // col group: cols [tc*4, tc*4+4)
    const int tr = tid >> 4;       // row group: rows [tr*4, tr*4+4)
    const int row0 = blockIdx.x * 64;

    float epsf = 0.f;
    if (COMBINE) epsf = 1.0f + epsp[0];

    float acc[4][4] = {};

    for (int kc = 0; kc < K; kc += 64) {
        // load W chunk [64 x 64], coalesced
#pragma unroll
        for (int i = 0; i < 16; ++i) {
            int idx = tid + i * 256;
            int k = idx >> 6, c = idx & 63;
            sW[k][c] = W[(kc + k) * 64 + c];
        }
        // load / combine X chunk [64 rows x 64 k], coalesced
#pragma unroll
        for (int i = 0; i < 16; ++i) {
            int idx = tid + i * 256;
            int r = idx >> 6, kk = idx & 63;
            int row = row0 + r;
            float v = 0.f;
            if (row < N_NODES) {
                if (COMBINE) {
                    float a = A[row * K + kc + kk];
                    float g = G[row * K + kc + kk];
                    v = fmaxf(fmaf(epsf, a, g) + preb[kc + kk], 0.f);
                } else {
                    v = A[row * K + kc + kk];
                }
            }
            sX[r][kk] = v;
        }
        __syncthreads();

#pragma unroll
        for (int k = 0; k < 64; k += 4) {
            float4 wv0 = *(const float4*)&sW[k + 0][tc * 4];
            float4 wv1 = *(const float4*)&sW[k + 1][tc * 4];
            float4 wv2 = *(const float4*)&sW[k + 2][tc * 4];
            float4 wv3 = *(const float4*)&sW[k + 3][tc * 4];
#pragma unroll
            for (int i = 0; i < 4; ++i) {
                float4 xv = *(const float4*)&sX[tr * 4 + i][k];
                acc[i][0] += xv.x * wv0.x + xv.y * wv1.x + xv.z * wv2.x + xv.w * wv3.x;
                acc[i][1] += xv.x * wv0.y + xv.y * wv1.y + xv.z * wv2.y + xv.w * wv3.y;
                acc[i][2] += xv.x * wv0.z + xv.y * wv1.z + xv.z * wv2.z + xv.w * wv3.z;
                acc[i][3] += xv.x * wv0.w + xv.y * wv1.w + xv.z * wv2.w + xv.w * wv3.w;
            }
        }
        __syncthreads();
    }

    // epilogue
#pragma unroll
    for (int i = 0; i < 4; ++i) {
        int row = row0 + tr * 4 + i;
        if (row < N_NODES) {
            float4 o = make_float4(acc[i][0], acc[i][1], acc[i][2], acc[i][3]);
            if (EPI) {
                const float4 bv = *(const float4*)&bias[tc * 4];
                o.x = fmaxf(o.x + bv.x, 0.f);
                o.y = fmaxf(o.y + bv.y, 0.f);
                o.z = fmaxf(o.z + bv.z, 0.f);
                o.w = fmaxf(o.w + bv.w, 0.f);
            }
            *(float4*)&out[row * 64 + tc * 4] = o;
        }
    }
}

// ---------------- edge aggregation: agg[dst] += y[src] ----------------------
// edge_index delivered as int32 by the harness (int64 inputs are narrowed).
__global__ void __launch_bounds__(256) edge_agg_kernel(
    const float* __restrict__ y, const int* __restrict__ ei,
    float* __restrict__ agg)
{
    int t = blockIdx.x * blockDim.x + threadIdx.x;
    if (t >= N_EDGES * 16) return;
    int e  = t >> 4;
    int c4 = t & 15;
    int src = __ldg(&ei[e]);
    int dst = __ldg(&ei[N_EDGES + e]);
    float4 v = *(const float4*)(y + (size_t)src * 64 + c4 * 4);
    float* p = agg + (size_t)dst * 64 + c4 * 4;
    asm volatile("red.global.add.v4.f32 [%0], {%1,%2,%3,%4};"
                 :: "l"(p), "f"(v.x), "f"(v.y), "f"(v.z), "f"(v.w) : "memory");
}

// ---------------- graph pooling: pooled[batch[n]] += h[n] -------------------
__global__ void __launch_bounds__(256) pool_kernel(
    const float* __restrict__ h, const int* __restrict__ batch,
    float* __restrict__ pooled)
{
    int t = blockIdx.x * blockDim.x + threadIdx.x;
    if (t >= N_NODES * 16) return;
    int n  = t >> 4;
    int c4 = t & 15;
    int g = __ldg(&batch[n]);
    float4 v = *(const float4*)(h + (size_t)n * 64 + c4 * 4);
    float* p = pooled + (size_t)g * 64 + c4 * 4;
    asm volatile("red.global.add.v4.f32 [%0], {%1,%2,%3,%4};"
                 :: "l"(p), "f"(v.x), "f"(v.y), "f"(v.z), "f"(v.w) : "memory");
}

// ---------------- head: logits + log_softmax --------------------------------
__global__ void __launch_bounds__(256) head_kernel(
    const float* __restrict__ pooled, const float* __restrict__ fcw,
    const float* __restrict__ fcb, float* __restrict__ out)
{
    int g = blockIdx.x * blockDim.x + threadIdx.x;
    if (g >= N_GRAPHS) return;
    float logit[OUT_CH];
#pragma unroll
    for (int j = 0; j < OUT_CH; ++j) logit[j] = __ldg(&fcb[j]);
#pragma unroll 8
    for (int k = 0; k < HID; ++k) {
        float p = pooled[g * HID + k];
#pragma unroll
        for (int j = 0; j < OUT_CH; ++j)
            logit[j] += p * __ldg(&fcw[k * OUT_CH + j]);
    }
    float m = logit[0];
#pragma unroll
    for (int j = 1; j < OUT_CH; ++j) m = fmaxf(m, logit[j]);
    float s = 0.f;
#pragma unroll
    for (int j = 0; j < OUT_CH; ++j) s += __expf(logit[j] - m);
    float ls = m + logf(s);
#pragma unroll
    for (int j = 0; j < OUT_CH; ++j) out[g * OUT_CH + j] = logit[j] - ls;
}

// ---------------- launch ----------------------------------------------------
extern "C" void kernel_launch(void* const* d_in, const int* in_sizes, int n_in,
                              void* d_out, int out_size)
{
    const float* x    = (const float*)d_in[0];
    const int*   ei   = (const int*)d_in[1];
    const int*   batch= (const int*)d_in[2];
    const float* eps0 = (const float*)d_in[3];
    const float* w0a  = (const float*)d_in[4];
    const float* b0a  = (const float*)d_in[5];
    const float* w0b  = (const float*)d_in[6];
    const float* b0b  = (const float*)d_in[7];
    const float* eps1 = (const float*)d_in[8];
    const float* w1a  = (const float*)d_in[9];
    const float* b1a  = (const float*)d_in[10];
    const float* w1b  = (const float*)d_in[11];
    const float* b1b  = (const float*)d_in[12];
    const float* fcw  = (const float*)d_in[13];
    const float* fcb  = (const float*)d_in[14];
    float*       out  = (float*)d_out;

    float *bufA, *bufB, *bufC, *pooled;
    cudaGetSymbolAddress((void**)&bufA, g_bufA);
    cudaGetSymbolAddress((void**)&bufB, g_bufB);
    cudaGetSymbolAddress((void**)&bufC, g_bufC);
    cudaGetSymbolAddress((void**)&pooled, g_pooled);

    const int gemm_blocks = (N_NODES + 63) / 64;   // 782
    const int edge_threads = N_EDGES * 16;
    const int edge_blocks = (edge_threads + 255) / 256;
    const int node4 = N_NODES * HID / 4;
    const int zero_blocks = 512;
    const int pool_threads = N_NODES * 16;
    const int pool_blocks = (pool_threads + 255) / 256;

    // Layer 0:  y0 = x @ w0a  (push linear through aggregation)
    linear_kernel<IN_CH, false, false><<<gemm_blocks, 256>>>(
        x, nullptr, nullptr, nullptr, w0a, nullptr, bufA);
    zero_kernel<<<zero_blocks, 256>>>((float4*)bufB, node4);
    edge_agg_kernel<<<edge_blocks, 256>>>(bufA, ei, bufB);
    // h0 = relu( relu((1+eps0)*y0 + agg0 + b0a) @ w0b + b0b )
    linear_kernel<HID, true, true><<<gemm_blocks, 256>>>(
        bufA, bufB, eps0, b0a, w0b, b0b, bufC);

    // Layer 1:  y1 = h0 @ w1a
    linear_kernel<HID, false, false><<<gemm_blocks, 256>>>(
        bufC, nullptr, nullptr, nullptr, w1a, nullptr, bufA);
    zero_kernel<<<zero_blocks, 256>>>((float4*)bufB, node4);
    edge_agg_kernel<<<edge_blocks, 256>>>(bufA, ei, bufB);
    // h1 = relu( relu((1+eps1)*y1 + agg1 + b1a) @ w1b + b1b )
    linear_kernel<HID, true, true><<<gemm_blocks, 256>>>(
        bufA, bufB, eps1, b1a, w1b, b1b, bufC);

    // Pool + head
    zero_kernel<<<8, 256>>>((float4*)pooled, N_GRAPHS * HID / 4);
    pool_kernel<<<pool_blocks, 256>>>(bufC, batch, pooled);
    head_kernel<<<2, 256>>>(pooled, fcw, fcb, out);
}